// round 6
// baseline (speedup 1.0000x reference)
#include <cuda_runtime.h>

#define Nn 50000
#define Ee 800000
#define Dd 96
#define TR 64            // rows per GEMM block
#define WT_STRIDE 98     // padded stride of transposed W (8B-aligned, conflict-free)

// ---------------------------------------------------------------------------
// Scratch (__device__ globals — no allocation allowed)
// ---------------------------------------------------------------------------
__device__ float4 g_h4[Nn * Dd / 4];     // hidden layer output (float4 => 16B aligned)
__device__ int    g_deg[Nn];             // per-dst degree
__device__ int    g_off[Nn];             // exclusive CSR offsets
__device__ int    g_pos[Nn];             // fill cursors
__device__ int    g_srcs[Ee];            // CSR column indices (src ids)
__device__ int    g_bsum[64];            // scan block sums

// ---------------------------------------------------------------------------
// CSR build
// ---------------------------------------------------------------------------
__global__ void k_zero_counts() {
    int i = blockIdx.x * blockDim.x + threadIdx.x;
    if (i < Nn) { g_deg[i] = 0; g_pos[i] = 0; }
}

__global__ void __launch_bounds__(256)
k_hist(const int* __restrict__ ei) {
    int e = blockIdx.x * blockDim.x + threadIdx.x;
    if (e >= Ee) return;
    int d = ei[Ee + e];
    if ((unsigned)d < (unsigned)Nn) atomicAdd(&g_deg[d], 1);
}

// Hierarchical scan: per-block exclusive scan + block sums
__global__ void k_scan1() {
    __shared__ int sm[1024];
    int i = blockIdx.x * 1024 + threadIdx.x;
    int v = (i < Nn) ? g_deg[i] : 0;
    sm[threadIdx.x] = v;
    __syncthreads();
    for (int off = 1; off < 1024; off <<= 1) {
        int t = (threadIdx.x >= off) ? sm[threadIdx.x - off] : 0;
        __syncthreads();
        sm[threadIdx.x] += t;
        __syncthreads();
    }
    if (i < Nn) g_off[i] = sm[threadIdx.x] - v;       // block-local exclusive
    if (threadIdx.x == 1023) g_bsum[blockIdx.x] = sm[1023];
}

// Exclusive scan of the (49) block sums — single tiny block
__global__ void k_scan2() {
    __shared__ int sm[64];
    int nblk = (Nn + 1023) / 1024;
    int v = (threadIdx.x < nblk) ? g_bsum[threadIdx.x] : 0;
    sm[threadIdx.x] = v;
    __syncthreads();
    for (int off = 1; off < 64; off <<= 1) {
        int t = (threadIdx.x >= off) ? sm[threadIdx.x - off] : 0;
        __syncthreads();
        sm[threadIdx.x] += t;
        __syncthreads();
    }
    g_bsum[threadIdx.x] = sm[threadIdx.x] - v;        // exclusive
}

__global__ void k_scan3() {
    int i = blockIdx.x * 1024 + threadIdx.x;
    if (i < Nn) g_off[i] += g_bsum[blockIdx.x];
}

__global__ void __launch_bounds__(256)
k_fill(const int* __restrict__ ei) {
    int e = blockIdx.x * blockDim.x + threadIdx.x;
    if (e >= Ee) return;
    int s = ei[e];
    int d = ei[Ee + e];
    if ((unsigned)s >= (unsigned)Nn || (unsigned)d >= (unsigned)Nn) return;
    int slot = g_off[d] + atomicAdd(&g_pos[d], 1);
    g_srcs[slot] = s;
}

// ---------------------------------------------------------------------------
// Fused per-layer kernel:
//   out[r] = relu?( segsum(X[src], dst=r) @ W_rel + bias + X[r] @ W_root )
// Block: 192 threads (tx=0..23, ty=0..7), 64 rows per block.
// Pass 0: warp-per-row gather of neighbor sums straight into the smem A-tile,
//         then A @ W_rel accumulated via packed f32x2 FMA (pack along K:
//         acc lane0 = even-k partial dot, lane1 = odd-k; reduced at epilogue).
// Pass 1: X-tile loaded, X @ W_root accumulated into the same accumulators.
// W is stored transposed in smem (shWT[c][k], stride 98) so both A and W
// inner-loop operands are natively k-contiguous 8-byte loads — no packing ops.
// ---------------------------------------------------------------------------
__global__ void __launch_bounds__(192, 2)
k_fused(const float* __restrict__ xin,
        const float* __restrict__ Wrel,
        const float* __restrict__ bias,
        const float* __restrict__ Wroot,
        float* out_param,
        int use_h_in, int use_h_out, int do_relu) {
    extern __shared__ float sm[];
    float* shWT = sm;                       // 96 * 98 floats
    float* shA  = sm + 96 * WT_STRIDE;      // 64 * 96 floats

    const float* X = use_h_in ? (const float*)g_h4 : xin;
    float*       O = use_h_out ? (float*)g_h4 : out_param;

    const int tx   = threadIdx.x;           // 0..23
    const int ty   = threadIdx.y;           // 0..7
    const int tid  = ty * 24 + tx;          // 0..191
    const int warp = tid >> 5;              // 0..5
    const int lane = tid & 31;
    const int row0 = blockIdx.x * TR;

    unsigned long long acc[8][4];
#pragma unroll
    for (int i = 0; i < 8; i++)
#pragma unroll
        for (int c = 0; c < 4; c++) acc[i][c] = 0ull;

    for (int pass = 0; pass < 2; pass++) {
        const float* W = pass ? Wroot : Wrel;
        __syncthreads();   // previous-pass readers done before smem overwrite

        // ---- load W transposed: shWT[c*98 + k] = W[k*96 + c] ----
#pragma unroll
        for (int m = 0; m < 48; m++) {
            int t = tid + 192 * m;          // 0..9215, coalesced read
            int k = t / 96, c = t - k * 96;
            shWT[c * WT_STRIDE + k] = W[t];
        }

        // ---- load A tile ----
        if (pass == 0) {
            // gather neighbor sums: one warp per row, lane c covers cols c,c+32,c+64
            for (int r = warp; r < TR; r += 6) {
                int gr = row0 + r;
                float a0 = 0.f, a1 = 0.f, a2 = 0.f;
                if (gr < Nn) {
                    int j = g_off[gr];
                    int end = j + g_deg[gr];
                    for (; j + 1 < end; j += 2) {
                        const float* r0 = X + g_srcs[j] * Dd;
                        const float* r1 = X + g_srcs[j + 1] * Dd;
                        a0 += r0[lane]      + r1[lane];
                        a1 += r0[lane + 32] + r1[lane + 32];
                        a2 += r0[lane + 64] + r1[lane + 64];
                    }
                    if (j < end) {
                        const float* r0 = X + g_srcs[j] * Dd;
                        a0 += r0[lane]; a1 += r0[lane + 32]; a2 += r0[lane + 64];
                    }
                }
                shA[r * Dd + lane]      = a0;
                shA[r * Dd + lane + 32] = a1;
                shA[r * Dd + lane + 64] = a2;
            }
        } else {
            // dense X tile, float4 coalesced
#pragma unroll
            for (int m = 0; m < 8; m++) {
                int idx = tid + 192 * m;    // 0..1535 (64 rows * 24 float4)
                int r  = idx / 24;
                int kc = idx - r * 24;
                int gr = row0 + r;
                float4 v = make_float4(0.f, 0.f, 0.f, 0.f);
                if (gr < Nn) v = reinterpret_cast<const float4*>(X + gr * Dd)[kc];
                reinterpret_cast<float4*>(shA + r * Dd)[kc] = v;
            }
        }
        __syncthreads();

        // ---- compute: packed f32x2 FMA, pack along K (k, k+1) ----
#pragma unroll 4
        for (int kk = 0; kk < Dd; kk += 2) {
            unsigned long long w[4];
#pragma unroll
            for (int c = 0; c < 4; c++)
                w[c] = *reinterpret_cast<const unsigned long long*>(
                           &shWT[(tx + 24 * c) * WT_STRIDE + kk]);
#pragma unroll
            for (int i = 0; i < 8; i++) {
                unsigned long long a = *reinterpret_cast<const unsigned long long*>(
                                           &shA[(ty * 8 + i) * Dd + kk]);
#pragma unroll
                for (int c = 0; c < 4; c++)
                    asm("fma.rn.f32x2 %0, %1, %2, %0;"
                        : "+l"(acc[i][c]) : "l"(a), "l"(w[c]));
            }
        }
    }

    // ---- epilogue: reduce packed lanes, add bias, relu, store ----
#pragma unroll
    for (int i = 0; i < 8; i++) {
        int gr = row0 + ty * 8 + i;
        if (gr < Nn) {
#pragma unroll
            for (int c = 0; c < 4; c++) {
                float lo = __uint_as_float((unsigned)(acc[i][c] & 0xFFFFFFFFull));
                float hi = __uint_as_float((unsigned)(acc[i][c] >> 32));
                float s = lo + hi + bias[tx + 24 * c];
                if (do_relu) s = fmaxf(s, 0.f);
                O[gr * Dd + tx + 24 * c] = s;
            }
        }
    }
}

// ---------------------------------------------------------------------------
extern "C" void kernel_launch(void* const* d_in, const int* in_sizes, int n_in,
                              void* d_out, int out_size) {
    const float* x    = (const float*)d_in[0];
    const int*   ei   = (const int*)d_in[1];   // int32 (JAX x64 disabled)
    const float* W1r  = (const float*)d_in[2];
    const float* b1   = (const float*)d_in[3];
    const float* W1o  = (const float*)d_in[4];
    const float* W2r  = (const float*)d_in[5];
    const float* b2   = (const float*)d_in[6];
    const float* W2o  = (const float*)d_in[7];
    float*       out  = (float*)d_out;

    const int smem_bytes = (96 * WT_STRIDE + TR * Dd) * (int)sizeof(float); // 62208
    cudaFuncSetAttribute(k_fused,
                         cudaFuncAttributeMaxDynamicSharedMemorySize, smem_bytes);

    const int node_blocks  = (Nn + 255) / 256;
    const int edge_blocks  = (Ee + 255) / 256;
    const int scan_blocks  = (Nn + 1023) / 1024;     // 49
    const int fused_blocks = (Nn + TR - 1) / TR;     // 782

    // ---- CSR build (shared by both layers) ----
    k_zero_counts<<<node_blocks, 256>>>();
    k_hist<<<edge_blocks, 256>>>(ei);
    k_scan1<<<scan_blocks, 1024>>>();
    k_scan2<<<1, 64>>>();
    k_scan3<<<scan_blocks, 1024>>>();
    k_fill<<<edge_blocks, 256>>>(ei);

    // ---- Layer 1: h = relu(agg(x) @ W1r + b1 + x @ W1o) ----
    k_fused<<<fused_blocks, dim3(24, 8), smem_bytes>>>(
        x, W1r, b1, W1o, out, /*use_h_in=*/0, /*use_h_out=*/1, /*do_relu=*/1);

    // ---- Layer 2: out = agg(h) @ W2r + b2 + h @ W2o ----
    k_fused<<<fused_blocks, dim3(24, 8), smem_bytes>>>(
        x, W2r, b2, W2o, out, /*use_h_in=*/1, /*use_h_out=*/0, /*do_relu=*/0);
}

// round 7
// speedup vs baseline: 1.1303x; 1.1303x over previous
#include <cuda_runtime.h>

#define Nn 50000
#define Ee 800000
#define Dd 96
#define TR 64            // rows per GEMM block
#define WT_STRIDE 98     // padded stride of transposed W (8B-aligned, conflict-free)

// ---------------------------------------------------------------------------
// Scratch (__device__ globals — no allocation allowed)
// ---------------------------------------------------------------------------
__device__ float4 g_agg4[Nn * Dd / 4];   // aggregated neighbor features
__device__ float4 g_h4[Nn * Dd / 4];     // hidden layer output
__device__ int    g_deg[Nn];             // per-dst degree
__device__ int    g_off[Nn];             // block-local exclusive offsets
__device__ int    g_pos[Nn];             // fill cursors
__device__ int    g_srcs[Ee];            // CSR column indices (src ids)
__device__ int    g_bsum[64];            // scan block sums (exclusive after k_scan2)

// ---------------------------------------------------------------------------
// CSR build
// ---------------------------------------------------------------------------
__global__ void k_zero_counts() {
    int i = blockIdx.x * blockDim.x + threadIdx.x;
    if (i < Nn) { g_deg[i] = 0; g_pos[i] = 0; }
}

// histogram of dst, 4 edges per thread via int4
__global__ void __launch_bounds__(256)
k_hist(const int* __restrict__ ei) {
    int t = blockIdx.x * blockDim.x + threadIdx.x;
    if (t >= Ee / 4) return;
    int4 d = reinterpret_cast<const int4*>(ei + Ee)[t];
    if ((unsigned)d.x < (unsigned)Nn) atomicAdd(&g_deg[d.x], 1);
    if ((unsigned)d.y < (unsigned)Nn) atomicAdd(&g_deg[d.y], 1);
    if ((unsigned)d.z < (unsigned)Nn) atomicAdd(&g_deg[d.z], 1);
    if ((unsigned)d.w < (unsigned)Nn) atomicAdd(&g_deg[d.w], 1);
}

// per-1024-block exclusive scan + block sums
__global__ void k_scan1() {
    __shared__ int sm[1024];
    int i = blockIdx.x * 1024 + threadIdx.x;
    int v = (i < Nn) ? g_deg[i] : 0;
    sm[threadIdx.x] = v;
    __syncthreads();
    for (int off = 1; off < 1024; off <<= 1) {
        int t = (threadIdx.x >= off) ? sm[threadIdx.x - off] : 0;
        __syncthreads();
        sm[threadIdx.x] += t;
        __syncthreads();
    }
    if (i < Nn) g_off[i] = sm[threadIdx.x] - v;       // block-local exclusive
    if (threadIdx.x == 1023) g_bsum[blockIdx.x] = sm[1023];
}

// exclusive scan of the 49 block sums
__global__ void k_scan2() {
    __shared__ int sm[64];
    int nblk = (Nn + 1023) / 1024;
    int v = (threadIdx.x < nblk) ? g_bsum[threadIdx.x] : 0;
    sm[threadIdx.x] = v;
    __syncthreads();
    for (int off = 1; off < 64; off <<= 1) {
        int t = (threadIdx.x >= off) ? sm[threadIdx.x - off] : 0;
        __syncthreads();
        sm[threadIdx.x] += t;
        __syncthreads();
    }
    g_bsum[threadIdx.x] = sm[threadIdx.x] - v;        // exclusive
}

// fill CSR columns; final offset = g_off + g_bsum (scan3 folded in here)
__global__ void __launch_bounds__(256)
k_fill(const int* __restrict__ ei) {
    int t = blockIdx.x * blockDim.x + threadIdx.x;
    if (t >= Ee / 4) return;
    int4 s = reinterpret_cast<const int4*>(ei)[t];
    int4 d = reinterpret_cast<const int4*>(ei + Ee)[t];
#pragma unroll
    for (int q = 0; q < 4; q++) {
        int ss = (&s.x)[q], dd = (&d.x)[q];
        if ((unsigned)ss >= (unsigned)Nn || (unsigned)dd >= (unsigned)Nn) continue;
        int slot = g_off[dd] + g_bsum[dd >> 10] + atomicAdd(&g_pos[dd], 1);
        g_srcs[slot] = ss;
    }
}

// ---------------------------------------------------------------------------
// Atomic-free segment sum: one warp per dst node, float4 lanes (24 active).
// One LDG.128 per edge-row, 4-edge unroll for MLP.
// ---------------------------------------------------------------------------
__global__ void __launch_bounds__(256)
k_gather(const float* __restrict__ xin, int use_h) {
    int warp = (blockIdx.x * blockDim.x + threadIdx.x) >> 5;
    if (warp >= Nn) return;
    int lane = threadIdx.x & 31;
    if (lane >= 24) return;
    const float4* feat = use_h ? (const float4*)g_h4
                               : reinterpret_cast<const float4*>(xin);
    int j   = g_off[warp] + g_bsum[warp >> 10];
    int end = j + g_deg[warp];
    float ax = 0.f, ay = 0.f, az = 0.f, aw = 0.f;
    for (; j + 3 < end; j += 4) {
        int s0 = g_srcs[j], s1 = g_srcs[j + 1], s2 = g_srcs[j + 2], s3 = g_srcs[j + 3];
        float4 v0 = feat[s0 * 24 + lane];
        float4 v1 = feat[s1 * 24 + lane];
        float4 v2 = feat[s2 * 24 + lane];
        float4 v3 = feat[s3 * 24 + lane];
        ax += (v0.x + v1.x) + (v2.x + v3.x);
        ay += (v0.y + v1.y) + (v2.y + v3.y);
        az += (v0.z + v1.z) + (v2.z + v3.z);
        aw += (v0.w + v1.w) + (v2.w + v3.w);
    }
    for (; j < end; j++) {
        float4 v = feat[g_srcs[j] * 24 + lane];
        ax += v.x; ay += v.y; az += v.z; aw += v.w;
    }
    g_agg4[warp * 24 + lane] = make_float4(ax, ay, az, aw);
}

// ---------------------------------------------------------------------------
// Dual matvec: out[r] = relu?( agg[r] @ W_rel + bias + X[r] @ W_root )
// Packed f32x2 FMA along K (acc.lo = even-k dot, acc.hi = odd-k; reduced at
// epilogue). W transposed in smem (stride 98) so both operands are LDS.64.
// Block 192 threads (tx 0..23 = col group tx,tx+24,tx+48,tx+72; ty 0..7 = 8 rows).
// ---------------------------------------------------------------------------
__global__ void __launch_bounds__(192, 3)
k_gemm(const float* __restrict__ xin,
       const float* __restrict__ Wrel,
       const float* __restrict__ bias,
       const float* __restrict__ Wroot,
       float* out_param,
       int use_h_in, int use_h_out, int do_relu) {
    extern __shared__ float sm[];
    float* shWT = sm;                       // 96 * 98 floats
    float* shA  = sm + 96 * WT_STRIDE;      // 64 * 96 floats

    const float* X = use_h_in ? (const float*)g_h4 : xin;
    float*       O = use_h_out ? (float*)g_h4 : out_param;

    const int tx   = threadIdx.x;           // 0..23
    const int ty   = threadIdx.y;           // 0..7
    const int tid  = ty * 24 + tx;          // 0..191
    const int row0 = blockIdx.x * TR;

    unsigned long long acc[8][4];
#pragma unroll
    for (int i = 0; i < 8; i++)
#pragma unroll
        for (int c = 0; c < 4; c++) acc[i][c] = 0ull;

    for (int pass = 0; pass < 2; pass++) {
        const float* W = pass ? Wroot : Wrel;
        const float* A = pass ? X : (const float*)g_agg4;
        __syncthreads();

        // load W transposed: shWT[c*98 + k] = W[k*96 + c]
#pragma unroll
        for (int m = 0; m < 12; m++) {
            int t4 = tid + 192 * m;                   // float4 index, coalesced read
            float4 v = reinterpret_cast<const float4*>(W)[t4];
            int t = t4 * 4;
            int k = t / 96, c = t - k * 96;
            shWT[(c + 0) * WT_STRIDE + k] = v.x;
            shWT[(c + 1) * WT_STRIDE + k] = v.y;
            shWT[(c + 2) * WT_STRIDE + k] = v.z;
            shWT[(c + 3) * WT_STRIDE + k] = v.w;
        }
        // load A tile: 64 rows * 24 float4, coalesced
#pragma unroll
        for (int m = 0; m < 8; m++) {
            int idx = tid + 192 * m;
            int r  = idx / 24;
            int kc = idx - r * 24;
            int gr = row0 + r;
            float4 v = make_float4(0.f, 0.f, 0.f, 0.f);
            if (gr < Nn) v = reinterpret_cast<const float4*>(A + gr * Dd)[kc];
            reinterpret_cast<float4*>(shA + r * Dd)[kc] = v;
        }
        __syncthreads();

#pragma unroll 4
        for (int kk = 0; kk < Dd; kk += 2) {
            unsigned long long w[4];
#pragma unroll
            for (int c = 0; c < 4; c++)
                w[c] = *reinterpret_cast<const unsigned long long*>(
                           &shWT[(tx + 24 * c) * WT_STRIDE + kk]);
#pragma unroll
            for (int i = 0; i < 8; i++) {
                unsigned long long a = *reinterpret_cast<const unsigned long long*>(
                                           &shA[(ty * 8 + i) * Dd + kk]);
#pragma unroll
                for (int c = 0; c < 4; c++)
                    asm("fma.rn.f32x2 %0, %1, %2, %0;"
                        : "+l"(acc[i][c]) : "l"(a), "l"(w[c]));
            }
        }
    }

    // epilogue: reduce packed halves, add bias, relu, store
#pragma unroll
    for (int i = 0; i < 8; i++) {
        int gr = row0 + ty * 8 + i;
        if (gr < Nn) {
#pragma unroll
            for (int c = 0; c < 4; c++) {
                float lo = __uint_as_float((unsigned)(acc[i][c] & 0xFFFFFFFFull));
                float hi = __uint_as_float((unsigned)(acc[i][c] >> 32));
                float s = lo + hi + bias[tx + 24 * c];
                if (do_relu) s = fmaxf(s, 0.f);
                O[gr * Dd + tx + 24 * c] = s;
            }
        }
    }
}

// ---------------------------------------------------------------------------
extern "C" void kernel_launch(void* const* d_in, const int* in_sizes, int n_in,
                              void* d_out, int out_size) {
    const float* x    = (const float*)d_in[0];
    const int*   ei   = (const int*)d_in[1];   // int32 (JAX x64 disabled)
    const float* W1r  = (const float*)d_in[2];
    const float* b1   = (const float*)d_in[3];
    const float* W1o  = (const float*)d_in[4];
    const float* W2r  = (const float*)d_in[5];
    const float* b2   = (const float*)d_in[6];
    const float* W2o  = (const float*)d_in[7];
    float*       out  = (float*)d_out;

    const int smem_bytes = (96 * WT_STRIDE + TR * Dd) * (int)sizeof(float); // 62208
    cudaFuncSetAttribute(k_gemm,
                         cudaFuncAttributeMaxDynamicSharedMemorySize, smem_bytes);

    const int node_blocks   = (Nn + 255) / 256;
    const int e4_blocks     = (Ee / 4 + 255) / 256;
    const int scan_blocks   = (Nn + 1023) / 1024;       // 49
    const int gather_blocks = (Nn * 32 + 255) / 256;
    const int gemm_blocks   = (Nn + TR - 1) / TR;       // 782

    // ---- CSR build (shared by both layers) ----
    k_zero_counts<<<node_blocks, 256>>>();
    k_hist<<<e4_blocks, 256>>>(ei);
    k_scan1<<<scan_blocks, 1024>>>();
    k_scan2<<<1, 64>>>();
    k_fill<<<e4_blocks, 256>>>(ei);

    // ---- Layer 1: h = relu(agg(x) @ W1r + b1 + x @ W1o) ----
    k_gather<<<gather_blocks, 256>>>(x, /*use_h=*/0);
    k_gemm<<<gemm_blocks, dim3(24, 8), smem_bytes>>>(
        x, W1r, b1, W1o, out, /*use_h_in=*/0, /*use_h_out=*/1, /*do_relu=*/1);

    // ---- Layer 2: out = agg(h) @ W2r + b2 + h @ W2o ----
    k_gather<<<gather_blocks, 256>>>(x, /*use_h=*/1);
    k_gemm<<<gemm_blocks, dim3(24, 8), smem_bytes>>>(
        x, W2r, b2, W2o, out, /*use_h_in=*/1, /*use_h_out=*/0, /*do_relu=*/0);
}